// round 10
// baseline (speedup 1.0000x reference)
#include <cuda_runtime.h>

#define TT   1024
#define BB   512
#define IND  64
#define HIDD 256
#define OUTD 32
#define TS   64            // timestep tile
#define NT   (TT / TS)     // 16 tiles
#define NTP  (TS / 2)      // 32 t-pairs per tile

typedef unsigned long long u64;

// Rounding contract (verified bitwise vs reference, rel_err 7.6e-8):
//  - dot products: single accumulator, ascending-k __fmaf_rn chain
//  - bias added after, separate __fadd_rn
//  - LIF: mem = __fmaf_rn(0.92, mem, cur) - reset (reset detached, prev mem)
//  - spike: (mem - 1.0f) > 0
// Bitwise-neutral exploits: fma.rn.f32x2 packs independent (t,t+1) chains
// (per-half IEEE rn); layer 2 = sparse ascending-k __fadd_rn sum over
// ballot-mask set bits, 4 chains round-robined (selected 0.0f add is exact).
// Layer 1 is k-major with 8 t-pair accumulators so each w-dup MOV feeds
// 8 FFMA2 (8-way ILP). mem2 of tile i-1 overlaps layer 2 of tile i (warp 0).

__device__ __forceinline__ u64 ffma2(u64 a, u64 b, u64 c) {
    u64 d;
    asm("fma.rn.f32x2 %0, %1, %2, %3;" : "=l"(d) : "l"(a), "l"(b), "l"(c));
    return d;
}
__device__ __forceinline__ u64 dup2(float w) {
    u64 d;
    asm("mov.b64 %0, {%1, %1};" : "=l"(d) : "f"(w));
    return d;
}
__device__ __forceinline__ float lo2(u64 v) { return ((float2*)&v)->x; }
__device__ __forceinline__ float hi2(u64 v) { return ((float2*)&v)->y; }

// one round-robin step of a sparse chain: add selected weight or 0.0f
#define SPARSE_STEP(m, a, wp)                              \
    {                                                      \
        int ko = __ffs(m);                                 \
        int kk = (ko > 0) ? ko - 1 : 0;                    \
        float v = wp[kk * OUTD];                           \
        a = __fadd_rn(a, (ko > 0) ? v : 0.0f);             \
        m &= m - 1;                                        \
    }

__global__ void __launch_bounds__(256, 2) snn_kernel(
    const float* __restrict__ x,    // [T, B, IN]
    const float* __restrict__ W1,   // [HID, IN]
    const float* __restrict__ b1,   // [HID]
    const float* __restrict__ W2,   // [OUT, HID]
    const float* __restrict__ b2,   // [OUT]
    float* __restrict__ out)        // [2, T, B, OUT] (spk2 then mem2)
{
    __shared__ __align__(16) float2   xk[IND][NTP];       // [k][t-pair], 16 KB
    __shared__ __align__(16) unsigned msk[2][TS][8];      // dbuf masks, 4 KB
    __shared__ __align__(16) float    w2s[HIDD][OUTD];    // W2^T, 32 KB
    __shared__ __align__(16) float    red[2][TS][OUTD];   // dbuf cur2, 16 KB

    const int b   = blockIdx.x;
    const int tid = threadIdx.x;   // layer 1: thread = hidden unit
    const int o   = tid & 31;
    const int tg  = tid >> 5;      // warp id

    for (int e = tid; e < OUTD * HIDD; e += 256) {
        w2s[e % HIDD][e / HIDD] = W2[e];
    }

    float w1r[IND];
    #pragma unroll
    for (int k = 0; k < IND; k++) w1r[k] = W1[tid * IND + k];

    const float b1h = b1[tid];
    const float b2o = b2[o];
    float mem1 = 0.0f, mem2 = 0.0f;

    for (int tile = 0; tile <= NT; tile++) {
        const int cb = tile & 1;

        // ---- a) stage x tile into xk[k][tp] = (x[2tp][k], x[2tp+1][k]) ----
        if (tile < NT) {
            const int t0 = tile * TS;
            #pragma unroll
            for (int i = 0; i < 2; i++) {
                int e  = tid + 256 * i;
                int tp = e & 31, kc = e >> 5;          // kc: 0..15
                float4 a = ((const float4*)(x + ((size_t)(t0 + 2 * tp)     * BB + b) * IND))[kc];
                float4 d = ((const float4*)(x + ((size_t)(t0 + 2 * tp + 1) * BB + b) * IND))[kc];
                xk[4 * kc + 0][tp] = make_float2(a.x, d.x);
                xk[4 * kc + 1][tp] = make_float2(a.y, d.y);
                xk[4 * kc + 2][tp] = make_float2(a.z, d.z);
                xk[4 * kc + 3][tp] = make_float2(a.w, d.w);
            }
        }
        __syncthreads();   // S_A: xk staged; red/msk handoff ordered

        // ---- b) layer 1: 4 sets x 8 t-pair accumulators, k-major ----
        if (tile < NT) {
            for (int s = 0; s < 4; s++) {              // t = 16s .. 16s+15
                u64 acc[8];
                #pragma unroll
                for (int j = 0; j < 8; j++) acc[j] = 0ull;
                const u64* base = (const u64*)&xk[0][8 * s];
                #pragma unroll 16
                for (int k = 0; k < IND; k++) {
                    u64 w = dup2(w1r[k]);
                    const ulonglong2* row = (const ulonglong2*)(base + (size_t)k * NTP);
                    ulonglong2 v0 = row[0];
                    ulonglong2 v1 = row[1];
                    ulonglong2 v2 = row[2];
                    ulonglong2 v3 = row[3];
                    acc[0] = ffma2(v0.x, w, acc[0]);
                    acc[1] = ffma2(v0.y, w, acc[1]);
                    acc[2] = ffma2(v1.x, w, acc[2]);
                    acc[3] = ffma2(v1.y, w, acc[3]);
                    acc[4] = ffma2(v2.x, w, acc[4]);
                    acc[5] = ffma2(v2.y, w, acc[5]);
                    acc[6] = ffma2(v3.x, w, acc[6]);
                    acc[7] = ffma2(v3.y, w, acc[7]);
                }
                // LIF ascending t over the 16 timesteps of this set
                #pragma unroll
                for (int j = 0; j < 8; j++) {
                    float cl = lo2(acc[j]);
                    float ch = hi2(acc[j]);
                    int   t  = 16 * s + 2 * j;
                    float cur1 = __fadd_rn(cl, b1h);
                    float r1f  = (mem1 > 1.0f) ? 1.0f : 0.0f;
                    mem1 = __fsub_rn(__fmaf_rn(0.92f, mem1, cur1), r1f);
                    unsigned bal = __ballot_sync(0xffffffffu,
                                       __fsub_rn(mem1, 1.0f) > 0.0f);
                    if (o == 0) msk[cb][t][tg] = bal;
                    cur1 = __fadd_rn(ch, b1h);
                    r1f  = (mem1 > 1.0f) ? 1.0f : 0.0f;
                    mem1 = __fsub_rn(__fmaf_rn(0.92f, mem1, cur1), r1f);
                    bal = __ballot_sync(0xffffffffu,
                                       __fsub_rn(mem1, 1.0f) > 0.0f);
                    if (o == 0) msk[cb][t + 1][tg] = bal;
                }
            }
        }
        __syncthreads();   // S_B: msk[cb] ready

        // ---- c1) warp 0: mem2 recurrence + store for tile-1 ----
        if (tile > 0 && tg == 0) {
            const int pb  = (tile - 1) & 1;
            const int t0p = (tile - 1) * TS;
            #pragma unroll 4
            for (int t = 0; t < TS; t++) {
                float cur2 = red[pb][t][o];
                float r2 = (mem2 > 1.0f) ? 1.0f : 0.0f;
                mem2 = __fsub_rn(__fmaf_rn(0.92f, mem2, cur2), r2);
                float s2 = (__fsub_rn(mem2, 1.0f) > 0.0f) ? 1.0f : 0.0f;
                size_t idx = ((size_t)(t0p + t) * BB + b) * OUTD + o;
                out[idx] = s2;                              // spk2_rec
                out[(size_t)TT * BB * OUTD + idx] = mem2;   // mem2_rec
            }
        }

        // ---- c2) layer 2: 8 chains/thread as two RR-4 passes -> red[cb] ----
        if (tile < NT) {
            #pragma unroll
            for (int pass = 0; pass < 2; pass++) {
                const int tb = tg + 32 * pass;   // chains t = tb + 8j, j=0..3
                float a0 = 0.0f, a1 = 0.0f, a2 = 0.0f, a3 = 0.0f;
                #pragma unroll
                for (int w = 0; w < 8; w++) {
                    unsigned m0 = msk[cb][tb][w];        // warp-uniform
                    unsigned m1 = msk[cb][tb + 8][w];
                    unsigned m2 = msk[cb][tb + 16][w];
                    unsigned m3 = msk[cb][tb + 24][w];
                    const float* wp = &w2s[w * 32][o];
                    while (m0 | m1 | m2 | m3) {          // uniform branch
                        SPARSE_STEP(m0, a0, wp)
                        SPARSE_STEP(m1, a1, wp)
                        SPARSE_STEP(m2, a2, wp)
                        SPARSE_STEP(m3, a3, wp)
                    }
                }
                red[cb][tb][o]      = __fadd_rn(a0, b2o);
                red[cb][tb + 8][o]  = __fadd_rn(a1, b2o);
                red[cb][tb + 16][o] = __fadd_rn(a2, b2o);
                red[cb][tb + 24][o] = __fadd_rn(a3, b2o);
            }
        }
        // no barrier here: next S_A orders red/msk handoff
    }
}

extern "C" void kernel_launch(void* const* d_in, const int* in_sizes, int n_in,
                              void* d_out, int out_size) {
    const float* x  = (const float*)d_in[0];  // spike_input [1024,512,64]
    const float* W1 = (const float*)d_in[1];  // [256,64]
    const float* b1 = (const float*)d_in[2];  // [256]
    const float* W2 = (const float*)d_in[3];  // [32,256]
    const float* b2 = (const float*)d_in[4];  // [32]
    float* out = (float*)d_out;               // 2*1024*512*32 floats

    snn_kernel<<<BB, 256>>>(x, W1, b1, W2, b2, out);
}